// round 17
// baseline (speedup 1.0000x reference)
#include <cuda_runtime.h>
#include <cuda_fp16.h>
#include <cstdint>

#define N_NODES 100000
#define N_EDGES 1600000

#define SCAN_BLK 1024
#define N_SCAN_BLOCKS ((N_NODES + SCAN_BLK - 1) / SCAN_BLK)   // 98

#define FLAG_AGG (1ULL << 62)
#define FLAG_INC (2ULL << 62)

// Device-global scratch (no allocation allowed).
// g_count zero-initialized at load; re-zeroed by the scan after each use.
// g_pkt reset by k_count_conv each call (stream-ordered before the scan).
__device__ __align__(16) float  g_agg[N_NODES * 64];
__device__ __align__(16) __half g_xh[N_NODES * 64];
__device__ int g_count[N_NODES];
__device__ int g_off[N_NODES + 1];
__device__ int g_cursor[N_NODES];
__device__ int g_perm[N_EDGES];
__device__ unsigned long long g_pkt[N_SCAN_BLOCKS];

// ---------------------------------------------------------------------------
// Pass 1 (merged): dst histogram + x -> fp16 conversion + scan-state reset.
// 2 edges / thread (vectorized int2 + 2x float4).
// ---------------------------------------------------------------------------
__global__ void k_count_conv(const int* __restrict__ ei,
                             const float4* __restrict__ x4) {
    int p = blockIdx.x * blockDim.x + threadIdx.x;      // pair index
    if (blockIdx.x == 0 && threadIdx.x < N_SCAN_BLOCKS) g_pkt[threadIdx.x] = 0;
    if (p >= N_EDGES / 2) return;
    int e = p * 2;

    // x conversion: 2 x float4 -> 8 halves (16B store)
    float4 v0 = __ldg(x4 + e);
    float4 v1 = __ldg(x4 + e + 1);
    __half2 h0 = __floats2half2_rn(v0.x, v0.y);
    __half2 h1 = __floats2half2_rn(v0.z, v0.w);
    __half2 h2 = __floats2half2_rn(v1.x, v1.y);
    __half2 h3 = __floats2half2_rn(v1.z, v1.w);
    uint4 pk;
    pk.x = *reinterpret_cast<uint32_t*>(&h0);
    pk.y = *reinterpret_cast<uint32_t*>(&h1);
    pk.z = *reinterpret_cast<uint32_t*>(&h2);
    pk.w = *reinterpret_cast<uint32_t*>(&h3);
    reinterpret_cast<uint4*>(g_xh)[p] = pk;

    // histogram: 2 dst entries
    int2 d = __ldg(reinterpret_cast<const int2*>(ei + N_EDGES) + p);
    if ((unsigned)d.x < N_NODES) atomicAdd(&g_count[d.x], 1);
    if ((unsigned)d.y < N_NODES) atomicAdd(&g_count[d.y], 1);
}

// ---------------------------------------------------------------------------
// Pass 2: single-pass exclusive scan with decoupled lookback (98 blocks).
// ---------------------------------------------------------------------------
__global__ __launch_bounds__(SCAN_BLK) void k_scan_lb() {
    __shared__ int sdata[SCAN_BLK];
    __shared__ int s_exc;
    int tid = threadIdx.x, b = blockIdx.x;
    int i = b * SCAN_BLK + tid;
    int v = (i < N_NODES) ? g_count[i] : 0;
    sdata[tid] = v;
    __syncthreads();
    #pragma unroll
    for (int d = 1; d < SCAN_BLK; d <<= 1) {
        int t = (tid >= d) ? sdata[tid - d] : 0;
        __syncthreads();
        sdata[tid] += t;
        __syncthreads();
    }
    int incl = sdata[tid];
    int total = sdata[SCAN_BLK - 1];

    if (b == 0) {
        if (tid == 0) {
            s_exc = 0;
            atomicExch(&g_pkt[0], FLAG_INC | (unsigned long long)(unsigned)total);
        }
    } else {
        if (tid == 0)
            atomicExch(&g_pkt[b], FLAG_AGG | (unsigned long long)(unsigned)total);
        if (tid < 32) {
            int exc = 0;
            int look = b - 1;
            while (true) {
                int idx = look - 31 + tid;           // lane 31 reads 'look'
                unsigned long long p = 0;
                if (idx >= 0) {
                    do { p = atomicAdd(&g_pkt[idx], 0ULL); } while (p < FLAG_AGG);
                }
                int myval = (idx >= 0) ? (int)(p & 0xFFFFFFFFULL) : 0;
                unsigned incmask = __ballot_sync(0xFFFFFFFFu,
                                                 idx >= 0 && (p & FLAG_INC));
                if (incmask) {
                    int hi = 31 - __clz(incmask);    // closest INC predecessor
                    int c = (tid >= hi) ? myval : 0;
                    #pragma unroll
                    for (int o = 16; o; o >>= 1) c += __shfl_xor_sync(0xFFFFFFFFu, c, o);
                    exc += c;
                    break;
                } else {
                    int c = myval;
                    #pragma unroll
                    for (int o = 16; o; o >>= 1) c += __shfl_xor_sync(0xFFFFFFFFu, c, o);
                    exc += c;
                    look -= 32;
                }
            }
            if (tid == 0) {
                s_exc = exc;
                atomicExch(&g_pkt[b],
                           FLAG_INC | (unsigned long long)(unsigned)(exc + total));
            }
        }
    }
    __syncthreads();
    int exc = s_exc;

    if (i < N_NODES) {
        int off = exc + incl - v;
        g_off[i] = off;
        g_cursor[i] = off;
        g_count[i] = 0;
    }
    if (b == 0 && tid == 0) g_off[N_NODES] = N_EDGES;
}

// ---------------------------------------------------------------------------
// Pass 3: fill permutation: perm[pos] = src, grouped by dst. 2 edges/thread.
// ---------------------------------------------------------------------------
__global__ void k_fill(const int* __restrict__ ei) {
    int p = blockIdx.x * blockDim.x + threadIdx.x;
    if (p >= N_EDGES / 2) return;
    int2 s = __ldg(reinterpret_cast<const int2*>(ei) + p);
    int2 d = __ldg(reinterpret_cast<const int2*>(ei + N_EDGES) + p);
    if ((unsigned)d.x < N_NODES && (unsigned)s.x < N_NODES) {
        int pos = atomicAdd(&g_cursor[d.x], 1);
        g_perm[pos] = s.x;
    }
    if ((unsigned)d.y < N_NODES && (unsigned)s.y < N_NODES) {
        int pos = atomicAdd(&g_cursor[d.y], 1);
        g_perm[pos] = s.y;
    }
}

// ---------------------------------------------------------------------------
// Pass 4: segment gather-sum over fp16 x + fp32 (1+eps)*x self-term.
// 8 threads/node, thread q owns one 16B chunk (4 half2). 4-edge batches with
// HADD2 tree; NEXT batch's perm indices preloaded before the reduction so
// the perm->row dependency is off the critical path.
// ---------------------------------------------------------------------------
__device__ __forceinline__ __half2 u2h(uint32_t u) {
    return *reinterpret_cast<__half2*>(&u);
}

__global__ __launch_bounds__(256) void k_gather_h(const float4* __restrict__ x4,
                                                  const float* __restrict__ eps) {
    int tid = blockIdx.x * blockDim.x + threadIdx.x;
    int node = tid >> 3;
    int q = tid & 7;
    if (node >= N_NODES) return;

    float s = 1.0f + __ldg(eps);
    float4 a0 = __ldg(x4 + (size_t)node * 16 + q * 2);
    float4 a1 = __ldg(x4 + (size_t)node * 16 + q * 2 + 1);
    float acc0 = a0.x * s, acc1 = a0.y * s, acc2 = a0.z * s, acc3 = a0.w * s;
    float acc4 = a1.x * s, acc5 = a1.y * s, acc6 = a1.z * s, acc7 = a1.w * s;

    const __half* xh = g_xh;
    int j   = __ldg(&g_off[node]);
    int end = __ldg(&g_off[node + 1]);

    int s0 = 0, s1 = 0, s2 = 0, s3 = 0;
    bool have = (j + 4 <= end);
    if (have) {
        s0 = __ldg(&g_perm[j]);
        s1 = __ldg(&g_perm[j + 1]);
        s2 = __ldg(&g_perm[j + 2]);
        s3 = __ldg(&g_perm[j + 3]);
    }
    while (have) {
        uint4 u0 = *reinterpret_cast<const uint4*>(xh + (size_t)s0 * 64 + q * 8);
        uint4 u1 = *reinterpret_cast<const uint4*>(xh + (size_t)s1 * 64 + q * 8);
        uint4 u2 = *reinterpret_cast<const uint4*>(xh + (size_t)s2 * 64 + q * 8);
        uint4 u3 = *reinterpret_cast<const uint4*>(xh + (size_t)s3 * 64 + q * 8);

        // preload next batch's indices while row loads are in flight
        j += 4;
        have = (j + 4 <= end);
        if (have) {
            s0 = __ldg(&g_perm[j]);
            s1 = __ldg(&g_perm[j + 1]);
            s2 = __ldg(&g_perm[j + 2]);
            s3 = __ldg(&g_perm[j + 3]);
        }

        // level 1: pair sums (8 HADD2)
        __half2 p0 = __hadd2(u2h(u0.x), u2h(u1.x));
        __half2 p1 = __hadd2(u2h(u0.y), u2h(u1.y));
        __half2 p2 = __hadd2(u2h(u0.z), u2h(u1.z));
        __half2 p3 = __hadd2(u2h(u0.w), u2h(u1.w));
        __half2 r0 = __hadd2(u2h(u2.x), u2h(u3.x));
        __half2 r1 = __hadd2(u2h(u2.y), u2h(u3.y));
        __half2 r2 = __hadd2(u2h(u2.z), u2h(u3.z));
        __half2 r3 = __hadd2(u2h(u2.w), u2h(u3.w));
        // level 2: quad sums (4 HADD2)
        __half2 t0 = __hadd2(p0, r0);
        __half2 t1 = __hadd2(p1, r1);
        __half2 t2 = __hadd2(p2, r2);
        __half2 t3 = __hadd2(p3, r3);
        // convert once, accumulate fp32
        float2 f0 = __half22float2(t0);
        float2 f1 = __half22float2(t1);
        float2 f2 = __half22float2(t2);
        float2 f3 = __half22float2(t3);
        acc0 += f0.x; acc1 += f0.y; acc2 += f1.x; acc3 += f1.y;
        acc4 += f2.x; acc5 += f2.y; acc6 += f3.x; acc7 += f3.y;
    }
    for (; j < end; j++) {
        int sx = __ldg(&g_perm[j]);
        uint4 u = *reinterpret_cast<const uint4*>(xh + (size_t)sx * 64 + q * 8);
        float2 f;
        f = __half22float2(u2h(u.x)); acc0 += f.x; acc1 += f.y;
        f = __half22float2(u2h(u.y)); acc2 += f.x; acc3 += f.y;
        f = __half22float2(u2h(u.z)); acc4 += f.x; acc5 += f.y;
        f = __half22float2(u2h(u.w)); acc6 += f.x; acc7 += f.y;
    }

    float4* dst = reinterpret_cast<float4*>(g_agg) + (size_t)node * 16 + q * 2;
    dst[0] = make_float4(acc0, acc1, acc2, acc3);
    dst[1] = make_float4(acc4, acc5, acc6, acc7);
}

// ---------------------------------------------------------------------------
// Pass 5: out = relu(agg @ W1 + b1) @ W2 + b2 via tf32 mma.sync.m16n8k8.
// ---------------------------------------------------------------------------
#define N_TILES ((N_NODES + 63) / 64)      // 1563
#define MLP_GRID (148 * 4)

__device__ __forceinline__ uint32_t f2tf32(float v) {
    uint32_t r;
    asm("cvt.rna.tf32.f32 %0, %1;" : "=r"(r) : "f"(v));
    return r;
}

__device__ __forceinline__ void mma_tf32(float& c0, float& c1, float& c2, float& c3,
                                         uint32_t a0, uint32_t a1, uint32_t a2, uint32_t a3,
                                         uint32_t b0, uint32_t b1) {
    asm volatile(
        "mma.sync.aligned.m16n8k8.row.col.f32.tf32.tf32.f32 "
        "{%0,%1,%2,%3}, {%4,%5,%6,%7}, {%8,%9}, {%0,%1,%2,%3};"
        : "+f"(c0), "+f"(c1), "+f"(c2), "+f"(c3)
        : "r"(a0), "r"(a1), "r"(a2), "r"(a3), "r"(b0), "r"(b1));
}

extern __shared__ float smlp[];

__global__ __launch_bounds__(128) void k_mlp_tc(const float* __restrict__ W1,
                                                const float* __restrict__ b1,
                                                const float* __restrict__ W2,
                                                const float* __restrict__ b2,
                                                float* __restrict__ out) {
    uint32_t* sA   = (uint32_t*)smlp;              // [64][68] tf32 bits
    uint32_t* sH   = sA + 64 * 68;                 // [64][68] tf32 bits
    uint32_t* sW1B = sH + 64 * 68;                 // 4096
    uint32_t* sW2B = sW1B + 4096;                  // 1024
    float*    sb1  = (float*)(sW2B + 1024);        // [64]
    float*    sb2  = sb1 + 64;                     // [16]

    int t = threadIdx.x;
    int lane = t & 31, w = t >> 5;
    int g = lane >> 2, tig = lane & 3;

    for (int i = t; i < 4096; i += 128) {
        int l = i & 31, half = (i >> 5) & 1, kk = (i >> 6) & 7, nt = i >> 9;
        int gg = l >> 2, tt = l & 3;
        sW1B[i] = f2tf32(W1[(kk * 8 + tt + half * 4) * 64 + nt * 8 + gg]);
    }
    for (int i = t; i < 1024; i += 128) {
        int l = i & 31, half = (i >> 5) & 1, kk = (i >> 6) & 7, nt = i >> 9;
        int gg = l >> 2, tt = l & 3;
        sW2B[i] = f2tf32(W2[(kk * 8 + tt + half * 4) * 16 + nt * 8 + gg]);
    }
    if (t < 64) sb1[t] = b1[t];
    if (t < 16) sb2[t] = b2[t];

    for (int tile = blockIdx.x; tile < N_TILES; tile += gridDim.x) {
        int node0 = tile * 64;
        int nrows = N_NODES - node0; if (nrows > 64) nrows = 64;

        __syncthreads();
        for (int i = t; i < 1024; i += 128) {
            int r = i >> 4, c4 = (i & 15) * 4;
            float4 v = (r < nrows)
                ? *reinterpret_cast<const float4*>(&g_agg[(size_t)(node0 + r) * 64 + c4])
                : make_float4(0.f, 0.f, 0.f, 0.f);
            uint32_t* dst = &sA[r * 68 + c4];
            dst[0] = f2tf32(v.x); dst[1] = f2tf32(v.y);
            dst[2] = f2tf32(v.z); dst[3] = f2tf32(v.w);
        }
        __syncthreads();

        uint32_t af[32];
        #pragma unroll
        for (int k = 0; k < 8; k++) {
            int row0 = (w * 16 + g) * 68, row1 = (w * 16 + g + 8) * 68;
            af[k * 4 + 0] = sA[row0 + k * 8 + tig];
            af[k * 4 + 1] = sA[row1 + k * 8 + tig];
            af[k * 4 + 2] = sA[row0 + k * 8 + tig + 4];
            af[k * 4 + 3] = sA[row1 + k * 8 + tig + 4];
        }

        #pragma unroll
        for (int nt = 0; nt < 8; nt++) {
            float c0 = sb1[nt * 8 + 2 * tig], c1 = sb1[nt * 8 + 2 * tig + 1];
            float c2 = c0, c3 = c1;
            #pragma unroll
            for (int k = 0; k < 8; k++) {
                uint32_t b0 = sW1B[(nt * 8 + k) * 64 + lane];
                uint32_t b1r = sW1B[(nt * 8 + k) * 64 + 32 + lane];
                mma_tf32(c0, c1, c2, c3,
                         af[k * 4 + 0], af[k * 4 + 1], af[k * 4 + 2], af[k * 4 + 3],
                         b0, b1r);
            }
            int row0 = (w * 16 + g) * 68, row1 = (w * 16 + g + 8) * 68;
            sH[row0 + nt * 8 + 2 * tig]     = f2tf32(fmaxf(c0, 0.0f));
            sH[row0 + nt * 8 + 2 * tig + 1] = f2tf32(fmaxf(c1, 0.0f));
            sH[row1 + nt * 8 + 2 * tig]     = f2tf32(fmaxf(c2, 0.0f));
            sH[row1 + nt * 8 + 2 * tig + 1] = f2tf32(fmaxf(c3, 0.0f));
        }
        __syncwarp();

        uint32_t hf[32];
        #pragma unroll
        for (int k = 0; k < 8; k++) {
            int row0 = (w * 16 + g) * 68, row1 = (w * 16 + g + 8) * 68;
            hf[k * 4 + 0] = sH[row0 + k * 8 + tig];
            hf[k * 4 + 1] = sH[row1 + k * 8 + tig];
            hf[k * 4 + 2] = sH[row0 + k * 8 + tig + 4];
            hf[k * 4 + 3] = sH[row1 + k * 8 + tig + 4];
        }

        #pragma unroll
        for (int nt = 0; nt < 2; nt++) {
            float c0 = sb2[nt * 8 + 2 * tig], c1 = sb2[nt * 8 + 2 * tig + 1];
            float c2 = c0, c3 = c1;
            #pragma unroll
            for (int k = 0; k < 8; k++) {
                uint32_t b0 = sW2B[(nt * 8 + k) * 64 + lane];
                uint32_t b1r = sW2B[(nt * 8 + k) * 64 + 32 + lane];
                mma_tf32(c0, c1, c2, c3,
                         hf[k * 4 + 0], hf[k * 4 + 1], hf[k * 4 + 2], hf[k * 4 + 3],
                         b0, b1r);
            }
            int col = nt * 8 + 2 * tig;
            int r0 = node0 + w * 16 + g;
            int r2 = r0 + 8;
            if (r0 < N_NODES)
                *reinterpret_cast<float2*>(&out[(size_t)r0 * 16 + col]) = make_float2(c0, c1);
            if (r2 < N_NODES)
                *reinterpret_cast<float2*>(&out[(size_t)r2 * 16 + col]) = make_float2(c2, c3);
        }
    }
}

// ---------------------------------------------------------------------------
extern "C" void kernel_launch(void* const* d_in, const int* in_sizes, int n_in,
                              void* d_out, int out_size) {
    const float* x   = (const float*)d_in[0];
    const int*   ei  = (const int*)d_in[1];   // int64 downcast to int32 by harness
    const float* eps = (const float*)d_in[2];
    const float* W1  = (const float*)d_in[3];
    const float* b1  = (const float*)d_in[4];
    const float* W2  = (const float*)d_in[5];
    const float* b2  = (const float*)d_in[6];
    float*       out = (float*)d_out;

    const int PB = (N_EDGES / 2 + 255) / 256;   // 3125 (2 edges/thread)

    k_count_conv<<<PB, 256>>>(ei, (const float4*)x);
    k_scan_lb<<<N_SCAN_BLOCKS, SCAN_BLK>>>();
    k_fill<<<PB, 256>>>(ei);

    {
        long long total = (long long)N_NODES * 8;
        int blocks = (int)((total + 255) / 256);
        k_gather_h<<<blocks, 256>>>((const float4*)x, eps);
    }

    {
        size_t shbytes = (size_t)(64 * 68 * 2 + 4096 + 1024) * 4 + (64 + 16) * 4;
        cudaFuncSetAttribute(k_mlp_tc,
                             cudaFuncAttributeMaxDynamicSharedMemorySize,
                             (int)shbytes);
        k_mlp_tc<<<MLP_GRID, 128, shbytes>>>(W1, b1, W2, b2, out);
    }
}